// round 1
// baseline (speedup 1.0000x reference)
#include <cuda_runtime.h>
#include <cstdint>

// Problem constants
#define Bsz 4
#define Nq  100
#define Mt  50
#define HWP 65536          // H*W
#define KSPLIT 64
#define KCH (HWP / KSPLIT) // 1024 k-elements per CTA
#define KB  32             // k per smem stage
#define NSTAGE (KCH / KB)  // 32 stages

typedef unsigned long long ull;

// Scratch (device globals: no allocation allowed)
__device__ float g_G1[Bsz * Nq * Mt];     // sum_k t * x
__device__ float g_G2[Bsz * Nq * Mt];     // sum_k t * sigmoid(x)
__device__ float g_sn_sp[Bsz * Nq];       // sum_k softplus(x)  (= -sum log(1-pm))
__device__ float g_sn_pm[Bsz * Nq];       // sum_k sigmoid(x)
__device__ float g_sm_t[Bsz * Mt];        // sum_k t

__device__ __forceinline__ ull ffma2(ull a, ull b, ull c) {
    ull d;
    asm("fma.rn.f32x2 %0, %1, %2, %3;" : "=l"(d) : "l"(a), "l"(b), "l"(c));
    return d;
}

__global__ void zero_kernel() {
    int i = blockIdx.x * blockDim.x + threadIdx.x;
    if (i < Bsz * Nq * Mt) { g_G1[i] = 0.f; g_G2[i] = 0.f; }
    if (i < Bsz * Nq)      { g_sn_sp[i] = 0.f; g_sn_pm[i] = 0.f; }
    if (i < Bsz * Mt)      { g_sm_t[i] = 0.f; }
}

// Main kernel: grid (KSPLIT, Bsz), block 256 (250 active for compute).
// Each CTA covers the full [100 x 50] output tile for one (b, k-chunk).
__global__ __launch_bounds__(256, 2)
void cost_main(const float* __restrict__ X, const float* __restrict__ T)
{
    __shared__ float2 xs[Nq][KB + 1];   // (x, sigmoid(x)) pairs, padded rows
    __shared__ float  ts[Mt][KB + 1];

    const int tid   = threadIdx.x;
    const int b     = blockIdx.y;
    const int kbase = blockIdx.x * KCH;

    // loader roles (threads 0..199)
    const int  xr = tid >> 1, xh = tid & 1;   // x: row, half (16 floats each)
    const int  tr = tid >> 2, tq = tid & 3;   // t: row, quarter (8 floats each)
    const bool ld = (tid < 200);

    // compute roles (threads 0..249); 250..255 compute clamped garbage, never stored
    const bool active = (tid < 250);
    const int  ty = active ? (tid / 10) : 24;  // 0..24, n = ty + 25*i
    const int  tx = active ? (tid % 10) : 0;   // 0..9,  m = tx + 10*j

    const float* Xr = X + ((size_t)b * Nq + (ld ? xr : 0)) * HWP + xh * 16;
    const float* Tr = T + ((size_t)b * Mt + (ld ? tr : 0)) * HWP + tq * 8;

    ull acc[4][5];
    #pragma unroll
    for (int i = 0; i < 4; i++)
        #pragma unroll
        for (int j = 0; j < 5; j++) acc[i][j] = 0ull;

    float ssp = 0.f, spm = 0.f, stt = 0.f;
    float4 px[4], pt[2];

    auto ldst = [&](int s) {
        const int k = kbase + s * KB;
        if (ld) {
            #pragma unroll
            for (int j = 0; j < 4; j++) px[j] = *(const float4*)(Xr + k + j * 4);
            #pragma unroll
            for (int j = 0; j < 2; j++) pt[j] = *(const float4*)(Tr + k + j * 4);
        }
    };

    ldst(0);

    for (int s = 0; s < NSTAGE; s++) {
        __syncthreads();   // previous stage's FMA reads done
        if (ld) {
            #pragma unroll
            for (int j = 0; j < 4; j++) {
                float v[4] = {px[j].x, px[j].y, px[j].z, px[j].w};
                #pragma unroll
                for (int e = 0; e < 4; e++) {
                    float x  = v[e];
                    float ea = __expf(-fabsf(x));
                    float rr = __fdividef(1.f, 1.f + ea);
                    float sg = (x >= 0.f) ? rr : (1.f - rr);
                    ssp += fmaxf(x, 0.f) + __logf(1.f + ea);   // softplus(x)
                    spm += sg;
                    xs[xr][xh * 16 + j * 4 + e] = make_float2(x, sg);
                }
            }
            #pragma unroll
            for (int j = 0; j < 2; j++) {
                float v[4] = {pt[j].x, pt[j].y, pt[j].z, pt[j].w};
                #pragma unroll
                for (int e = 0; e < 4; e++) {
                    ts[tr][tq * 8 + j * 4 + e] = v[e];
                    stt += v[e];
                }
            }
        }
        __syncthreads();
        if (s + 1 < NSTAGE) ldst(s + 1);   // prefetch next stage under FMA

        #pragma unroll 4
        for (int k = 0; k < KB; k++) {
            ull xv[4], tb[5];
            #pragma unroll
            for (int i = 0; i < 4; i++)
                xv[i] = *(const ull*)&xs[ty + 25 * i][k];
            #pragma unroll
            for (int j = 0; j < 5; j++) {
                float tvv = ts[tx + 10 * j][k];
                asm("mov.b64 %0, {%1, %1};" : "=l"(tb[j]) : "f"(tvv));
            }
            #pragma unroll
            for (int i = 0; i < 4; i++)
                #pragma unroll
                for (int j = 0; j < 5; j++)
                    acc[i][j] = ffma2(xv[i], tb[j], acc[i][j]);
        }
    }

    // per-row reductions (no shuffles: partial warps; atomics are cheap here)
    if (ld) {
        atomicAdd(&g_sn_sp[b * Nq + xr], ssp);
        atomicAdd(&g_sn_pm[b * Nq + xr], spm);
        if (tq == 0 || true) atomicAdd(&g_sm_t[b * Mt + tr], stt * 0.f + stt); // one add per thread
    }

    if (active) {
        #pragma unroll
        for (int i = 0; i < 4; i++) {
            const int n = ty + 25 * i;
            #pragma unroll
            for (int j = 0; j < 5; j++) {
                const int m = tx + 10 * j;
                float2 a = *(float2*)&acc[i][j];  // (.x = sum t*x, .y = sum t*sig)
                atomicAdd(&g_G1[(b * Nq + n) * Mt + m], a.x);
                atomicAdd(&g_G2[(b * Nq + n) * Mt + m], a.y);
            }
        }
    }
}

__global__ void cost_epi(const float* __restrict__ logits,
                         const float* __restrict__ style,
                         const int* __restrict__ sids,
                         float* __restrict__ out)
{
    const int n = blockIdx.x;
    const int b = blockIdx.y;
    const int m = threadIdx.x;
    if (m >= Mt) return;

    const float l0 = logits[(b * Nq + n) * 2 + 0];
    const float l1 = logits[(b * Nq + n) * 2 + 1];
    const float p1 = __fdividef(1.f, 1.f + __expf(l0 - l1));

    const float* st = style + (b * Nq + n) * 4;
    const float s0 = st[0], s1 = st[1], s2 = st[2], s3 = st[3];
    const float mx = fmaxf(fmaxf(s0, s1), fmaxf(s2, s3));
    const float e0 = __expf(s0 - mx), e1 = __expf(s1 - mx);
    const float e2 = __expf(s2 - mx), e3 = __expf(s3 - mx);
    const float inv = __fdividef(1.f, e0 + e1 + e2 + e3);

    const float snsp = g_sn_sp[b * Nq + n];
    const float snpm = g_sn_pm[b * Nq + n];
    const float G1v  = g_G1[(b * Nq + n) * Mt + m];
    const float G2v  = g_G2[(b * Nq + n) * Mt + m];
    const float smt  = g_sm_t[b * Mt + m];

    // cost_mask = -(sum t*logit + sum log(1-pm))/HW = (snsp - G1)/HW
    const float cmask = (snsp - G1v) * (1.0f / (float)HWP);
    const float cdice = 1.f - __fdividef(2.f * G2v + 1.f, snpm + smt + 1.f);

    int sid = sids[b * Mt + m];
    sid = sid < 0 ? 0 : (sid > 3 ? 3 : sid);
    float pr = (sid == 0) ? e0 : (sid == 1) ? e1 : (sid == 2) ? e2 : e3;
    pr *= inv;

    float c = -2.f * p1 + 5.f * cmask + 5.f * cdice - pr;
    if (!isfinite(c)) c = isnan(c) ? 10000.f : (c > 0.f ? 10000.f : -10000.f);
    out[(b * Nq + n) * Mt + m] = c;
}

extern "C" void kernel_launch(void* const* d_in, const int* in_sizes, int n_in,
                              void* d_out, int out_size)
{
    const float* pred_logits = (const float*)d_in[0];  // [4,100,2]
    const float* pred_masks  = (const float*)d_in[1];  // [4,100,256,256]
    const float* pred_style  = (const float*)d_in[2];  // [4,100,4]
    const float* tgt_masks   = (const float*)d_in[3];  // [4,50,256,256]
    const int*   styles      = (const int*)d_in[4];    // [4,50]
    float* out = (float*)d_out;                        // [4,100,50]

    zero_kernel<<<(Bsz * Nq * Mt + 255) / 256, 256>>>();

    dim3 gmain(KSPLIT, Bsz);
    cost_main<<<gmain, 256>>>(pred_masks, tgt_masks);

    dim3 gepi(Nq, Bsz);
    cost_epi<<<gepi, 64>>>(pred_logits, pred_style, styles, out);
}

// round 3
// speedup vs baseline: 2.0080x; 2.0080x over previous
#include <cuda_runtime.h>
#include <cuda_bf16.h>
#include <cstdint>

// ---------------- problem constants ----------------
#define Bsz 4
#define Nq  100
#define Mt  50
#define HWP 65536
#define KS  64                  // k per stage
#define NKT (HWP / KS)          // 1024 k-tiles per batch
#define CTAS_PER_B 37           // 148 CTAs = one full wave
#define THREADS 512             // 16 warps

// smem buffer layout (per stage buffer, 1024-aligned):
//   A_x  [128 x 64] bf16  = 16384 B   (+0)
//   A_s  [128 x 64] bf16  = 16384 B   (+16384)
//   B_t  [ 64 x 64] bf16  =  8192 B   (+32768)
#define BUF_SZ 40960
#define SMEM_BYTES (2 * BUF_SZ + 1024)

// ---------------- scratch (device globals) ----------------
__device__ float g_G1[Bsz * Nq * Mt];   // sum_k t * x
__device__ float g_G2[Bsz * Nq * Mt];   // sum_k t * sigmoid(x)
__device__ float g_snpm[Bsz * Nq];      // sum_k sigmoid(x)
__device__ float g_snsp[Bsz * Nq];      // sum_k softplus(x)
__device__ float g_smt[Bsz * Mt];       // sum_k t

__device__ __forceinline__ uint32_t smem_u32(const void* p) {
    uint32_t a;
    asm("{ .reg .u64 t; cvta.to.shared.u64 t, %1; cvt.u32.u64 %0, t; }" : "=r"(a) : "l"(p));
    return a;
}
__device__ __forceinline__ uint32_t SW(uint32_t o) { return o ^ ((o >> 3) & 0x70); }

#define LDSM4(r0, r1, r2, r3, addr) \
    asm volatile("ldmatrix.sync.aligned.m8n8.x4.shared.b16 {%0,%1,%2,%3}, [%4];" \
                 : "=r"(r0), "=r"(r1), "=r"(r2), "=r"(r3) : "r"(addr))

#define MMA16816(c, a, b0, b1) \
    asm volatile("mma.sync.aligned.m16n8k16.row.col.f32.bf16.bf16.f32 " \
                 "{%0,%1,%2,%3},{%4,%5,%6,%7},{%8,%9},{%0,%1,%2,%3};" \
                 : "+f"((c)[0]), "+f"((c)[1]), "+f"((c)[2]), "+f"((c)[3]) \
                 : "r"((a)[0]), "r"((a)[1]), "r"((a)[2]), "r"((a)[3]), "r"(b0), "r"(b1))

__global__ void zero_kernel() {
    int i = blockIdx.x * blockDim.x + threadIdx.x;
    if (i < Bsz * Nq * Mt) { g_G1[i] = 0.f; g_G2[i] = 0.f; }
    if (i < Bsz * Nq)      { g_snpm[i] = 0.f; g_snsp[i] = 0.f; }
    if (i < Bsz * Mt)      { g_smt[i] = 0.f; }
}

__global__ void __launch_bounds__(THREADS, 1)
cost_main(const float* __restrict__ X, const float* __restrict__ T)
{
    extern __shared__ char dsm[];
    const uint32_t sb = (smem_u32(dsm) + 1023u) & ~1023u;

    const int tid = threadIdx.x;
    const int b   = blockIdx.y;
    const int r   = blockIdx.x;
    const int t0  = (r * NKT) / CTAS_PER_B;
    const int nst = ((r + 1) * NKT) / CTAS_PER_B - t0;

    // zero both stage buffers once (rows >=100 of A / >=50 of B stay zero forever)
    for (int i = tid; i < (2 * BUF_SZ) / 8; i += THREADS)
        asm volatile("st.shared.b64 [%0], %1;" :: "r"(sb + i * 8), "l"(0ull) : "memory");
    __syncthreads();
    // constant ones rows: A_x row 100 (-> sum_k t), B row 50 (-> sum_k sigma)
    const uint64_t ones8 = 0x3F803F803F803F80ull;
    if (tid < 16) {
        uint32_t o = SW(100u * 128u + (uint32_t)tid * 8u);
        asm volatile("st.shared.b64 [%0], %1;" :: "r"(sb + o), "l"(ones8) : "memory");
        asm volatile("st.shared.b64 [%0], %1;" :: "r"(sb + BUF_SZ + o), "l"(ones8) : "memory");
    } else if (tid < 32) {
        uint32_t o = SW(50u * 128u + (uint32_t)(tid - 16) * 8u) + 32768u;
        asm volatile("st.shared.b64 [%0], %1;" :: "r"(sb + o), "l"(ones8) : "memory");
        asm volatile("st.shared.b64 [%0], %1;" :: "r"(sb + BUF_SZ + o), "l"(ones8) : "memory");
    }
    __syncthreads();

    const float* Xb = X + (size_t)b * Nq * HWP;
    const float* Tb = T + (size_t)b * Mt * HWP;

    float4 la[4], lb[2];
    auto LOADS = [&](int s) {
        const int kb = (t0 + s) * KS;
        #pragma unroll
        for (int j = 0; j < 4; j++) {
            int idx = tid + THREADS * j;
            if (idx < 1600) {
                int row = idx >> 4, c4 = idx & 15;
                la[j] = *(const float4*)(Xb + (size_t)row * HWP + kb + c4 * 4);
            }
        }
        #pragma unroll
        for (int j = 0; j < 2; j++) {
            int idx = tid + THREADS * j;
            if (idx < 800) {
                int row = idx >> 4, c4 = idx & 15;
                lb[j] = *(const float4*)(Tb + (size_t)row * HWP + kb + c4 * 4);
            }
        }
    };
    LOADS(0);

    // per-warp mma geometry: warp w owns rows 16*(w/2), cols 32*(w&1)
    const int w = tid >> 5, l = tid & 31;
    const int Rr = (w >> 1) * 16, Cc = (w & 1) * 32;
    const uint32_t rowA  = (uint32_t)(Rr + (l & 15)) * 128u + (uint32_t)(l >> 4) * 16u;
    const uint32_t rowB0 = (uint32_t)(Cc + (l & 15)) * 128u + (uint32_t)(l >> 4) * 16u;
    const uint32_t rowB1 = rowB0 + 16u * 128u;

    float cx[4][4], cs[4][4];
    #pragma unroll
    for (int nb = 0; nb < 4; nb++)
        #pragma unroll
        for (int e = 0; e < 4; e++) { cx[nb][e] = 0.f; cs[nb][e] = 0.f; }

    float spm[4] = {0.f, 0.f, 0.f, 0.f};   // sum relu(x)
    float spl[4] = {0.f, 0.f, 0.f, 0.f};   // sum log2(1+e^-|x|)

    for (int s = 0; s < nst; s++) {
        const uint32_t BUF = sb + (uint32_t)(s & 1) * BUF_SZ;
        const uint32_t BTb = BUF + 32768u;

        // ---- convert: fp32 -> (bf16 x, bf16 sigmoid) + softplus partials ----
        #pragma unroll
        for (int j = 0; j < 4; j++) {
            int idx = tid + THREADS * j;
            if (idx < 1600) {
                int row = idx >> 4, c4 = idx & 15;
                float v[4] = {la[j].x, la[j].y, la[j].z, la[j].w};
                float sg[4];
                #pragma unroll
                for (int e = 0; e < 4; e++) {
                    float x = v[e], ea, lg;
                    asm("ex2.approx.f32 %0, %1;" : "=f"(ea) : "f"(-1.4426950408889634f * fabsf(x)));
                    float d = 1.f + ea;
                    asm("lg2.approx.f32 %0, %1;" : "=f"(lg) : "f"(d));
                    spm[j] += fmaxf(x, 0.f);
                    spl[j] += lg;
                    float y = fmaf(-0.4566f, ea, 0.9566f);       // ~1/d seed, d in (1,2]
                    y = fmaf(y, fmaf(-d, y, 1.f), y);            // Newton 1
                    y = fmaf(y, fmaf(-d, y, 1.f), y);            // Newton 2
                    sg[e] = (x >= 0.f) ? y : (1.f - y);
                }
                uint32_t xw0, xw1, sw0, sw1;
                asm("cvt.rn.bf16x2.f32 %0, %1, %2;" : "=r"(xw0) : "f"(v[1]),  "f"(v[0]));
                asm("cvt.rn.bf16x2.f32 %0, %1, %2;" : "=r"(xw1) : "f"(v[3]),  "f"(v[2]));
                asm("cvt.rn.bf16x2.f32 %0, %1, %2;" : "=r"(sw0) : "f"(sg[1]), "f"(sg[0]));
                asm("cvt.rn.bf16x2.f32 %0, %1, %2;" : "=r"(sw1) : "f"(sg[3]), "f"(sg[2]));
                uint32_t a = BUF + SW((uint32_t)row * 128u + (uint32_t)c4 * 8u);
                asm volatile("st.shared.v2.b32 [%0], {%1, %2};" :: "r"(a), "r"(xw0), "r"(xw1) : "memory");
                asm volatile("st.shared.v2.b32 [%0], {%1, %2};" :: "r"(a + 16384u), "r"(sw0), "r"(sw1) : "memory");
            }
        }
        #pragma unroll
        for (int j = 0; j < 2; j++) {
            int idx = tid + THREADS * j;
            if (idx < 800) {
                int row = idx >> 4, c4 = idx & 15;
                uint32_t w0, w1;
                asm("cvt.rn.bf16x2.f32 %0, %1, %2;" : "=r"(w0) : "f"(lb[j].y), "f"(lb[j].x));
                asm("cvt.rn.bf16x2.f32 %0, %1, %2;" : "=r"(w1) : "f"(lb[j].w), "f"(lb[j].z));
                uint32_t a = BTb + SW((uint32_t)row * 128u + (uint32_t)c4 * 8u);
                asm volatile("st.shared.v2.b32 [%0], {%1, %2};" :: "r"(a), "r"(w0), "r"(w1) : "memory");
            }
        }
        __syncthreads();

        if (s + 1 < nst) LOADS(s + 1);   // overlap gmem with mma phase

        // ---- mma phase on buffer (s&1) ----
        #pragma unroll
        for (int i = 0; i < 4; i++) {
            uint32_t aax = BUF + SW(rowA + 32u * i);
            uint32_t ax[4], as[4], q[4], p[4];
            LDSM4(ax[0], ax[1], ax[2], ax[3], aax);
            LDSM4(as[0], as[1], as[2], as[3], aax + 16384u);
            LDSM4(q[0], q[1], q[2], q[3], BTb + SW(rowB0 + 32u * i));
            LDSM4(p[0], p[1], p[2], p[3], BTb + SW(rowB1 + 32u * i));
            MMA16816(cx[0], ax, q[0], q[2]);
            MMA16816(cx[1], ax, q[1], q[3]);
            MMA16816(cx[2], ax, p[0], p[2]);
            MMA16816(cx[3], ax, p[1], p[3]);
            MMA16816(cs[0], as, q[0], q[2]);
            MMA16816(cs[1], as, q[1], q[3]);
            MMA16816(cs[2], as, p[0], p[2]);
            MMA16816(cs[3], as, p[1], p[3]);
        }
    }

    // ---- combine: softplus row sums ----
    #pragma unroll
    for (int j = 0; j < 4; j++) {
        int idx = tid + THREADS * j;
        if (idx < 1600) {
            int row = idx >> 4;
            atomicAdd(&g_snsp[b * Nq + row], spm[j] + 0.6931471805599453f * spl[j]);
        }
    }

    // ---- combine: accumulator fragments ----
    auto emit = [&](int rr, int m, float vx, float vs) {
        if (rr < Nq) {
            if (m < Mt) {
                atomicAdd(&g_G1[(b * Nq + rr) * Mt + m], vx);
                atomicAdd(&g_G2[(b * Nq + rr) * Mt + m], vs);
            } else if (m == Mt) {
                atomicAdd(&g_snpm[b * Nq + rr], vs);
            }
        } else if (rr == Nq && m < Mt) {
            atomicAdd(&g_smt[b * Mt + m], vx);
        }
    };
    #pragma unroll
    for (int nb = 0; nb < 4; nb++) {
        const int m0 = Cc + nb * 8 + (l & 3) * 2;
        const int r0 = Rr + (l >> 2);
        emit(r0,     m0,     cx[nb][0], cs[nb][0]);
        emit(r0,     m0 + 1, cx[nb][1], cs[nb][1]);
        emit(r0 + 8, m0,     cx[nb][2], cs[nb][2]);
        emit(r0 + 8, m0 + 1, cx[nb][3], cs[nb][3]);
    }
}

__global__ void cost_epi(const float* __restrict__ logits,
                         const float* __restrict__ style,
                         const int* __restrict__ sids,
                         float* __restrict__ out)
{
    const int n = blockIdx.x, b = blockIdx.y, m = threadIdx.x;
    if (m >= Mt) return;

    const float l0 = logits[(b * Nq + n) * 2 + 0];
    const float l1 = logits[(b * Nq + n) * 2 + 1];
    const float p1 = __fdividef(1.f, 1.f + __expf(l0 - l1));

    const float* st = style + (b * Nq + n) * 4;
    const float s0 = st[0], s1 = st[1], s2 = st[2], s3 = st[3];
    const float mx = fmaxf(fmaxf(s0, s1), fmaxf(s2, s3));
    const float e0 = __expf(s0 - mx), e1 = __expf(s1 - mx);
    const float e2 = __expf(s2 - mx), e3 = __expf(s3 - mx);
    const float inv = __fdividef(1.f, e0 + e1 + e2 + e3);

    const float snsp = g_snsp[b * Nq + n];
    const float snpm = g_snpm[b * Nq + n];
    const float G1v  = g_G1[(b * Nq + n) * Mt + m];
    const float G2v  = g_G2[(b * Nq + n) * Mt + m];
    const float smt  = g_smt[b * Mt + m];

    const float cmask = (snsp - G1v) * (1.0f / (float)HWP);
    const float cdice = 1.f - __fdividef(2.f * G2v + 1.f, snpm + smt + 1.f);

    int sid = sids[b * Mt + m];
    sid = sid < 0 ? 0 : (sid > 3 ? 3 : sid);
    float pr = (sid == 0) ? e0 : (sid == 1) ? e1 : (sid == 2) ? e2 : e3;
    pr *= inv;

    float c = -2.f * p1 + 5.f * cmask + 5.f * cdice - pr;
    if (!isfinite(c)) c = isnan(c) ? 10000.f : (c > 0.f ? 10000.f : -10000.f);
    out[(b * Nq + n) * Mt + m] = c;
}

extern "C" void kernel_launch(void* const* d_in, const int* in_sizes, int n_in,
                              void* d_out, int out_size)
{
    const float* pred_logits = (const float*)d_in[0];  // [4,100,2]
    const float* pred_masks  = (const float*)d_in[1];  // [4,100,256,256]
    const float* pred_style  = (const float*)d_in[2];  // [4,100,4]
    const float* tgt_masks   = (const float*)d_in[3];  // [4,50,256,256]
    const int*   styles      = (const int*)d_in[4];    // [4,50]
    float* out = (float*)d_out;                        // [4,100,50]

    cudaFuncSetAttribute(cost_main, cudaFuncAttributeMaxDynamicSharedMemorySize, SMEM_BYTES);

    zero_kernel<<<(Bsz * Nq * Mt + 255) / 256, 256>>>();
    dim3 gmain(CTAS_PER_B, Bsz);
    cost_main<<<gmain, THREADS, SMEM_BYTES>>>(pred_masks, tgt_masks);
    dim3 gepi(Nq, Bsz);
    cost_epi<<<gepi, 64>>>(pred_logits, pred_style, styles, out);
}